// round 4
// baseline (speedup 1.0000x reference)
#include <cuda_runtime.h>
#include <math.h>

#define THREADS 384
#define NWARP 12
#define PB 8

typedef unsigned long long u64;

// shared layout (floats)
#define OFF_W1KP 0          // [64][128][2]  fwd:  {W1[j][2k2], W1[j][2k2+1]}
#define OFF_W1JP 16384      // [64][128][2]  bwd:  {W1[2j2][k], W1[2j2+1][k]}
#define OFF_W0KP 32768      // [10][128][2]  fwd L0 (input 19 zero-padded to 20)
#define OFF_W0T  35328      // [19][128]     bwd-fused
#define OFF_B0   37760
#define OFF_B1   37888
#define OFF_WO   38016
#define OFF_STAGE 38144
#define WARP_STAGE 1568     // buf 1024 | hs 160 | dEs 384
#define SMEM_FLOATS (OFF_STAGE + NWARP * WARP_STAGE)

__device__ __forceinline__ float shx(float v, int m) {
    return __shfl_xor_sync(0xFFFFFFFFu, v, m);
}
__device__ __forceinline__ void ffma2(u64 &d, u64 a, u64 b) {
    asm("fma.rn.f32x2 %0, %1, %2, %0;" : "+l"(d) : "l"(a), "l"(b));
}
__device__ __forceinline__ float hadd2(u64 v) {
    return __uint_as_float((unsigned)v) + __uint_as_float((unsigned)(v >> 32));
}

__global__ void __launch_bounds__(THREADS, 1)
neural_sdf_kernel(const float* __restrict__ pos,
                  const float* __restrict__ grid,
                  const float* __restrict__ W0g,
                  const float* __restrict__ b0g,
                  const float* __restrict__ W1g,
                  const float* __restrict__ b1g,
                  const float* __restrict__ Wog,
                  const float* __restrict__ bog,
                  float* __restrict__ out,
                  int n_pts)
{
    extern __shared__ float sm[];
    float* W1kp = sm + OFF_W1KP;
    float* W1jp = sm + OFF_W1JP;
    float* W0kp = sm + OFF_W0KP;
    float* W0T  = sm + OFF_W0T;
    float* b0s  = sm + OFF_B0;
    float* b1s  = sm + OFF_B1;
    float* Wos  = sm + OFF_WO;

    const int tid = threadIdx.x;

    // ---- cooperative weight preload (k-pair interleaved layouts) ----
    for (int idx = tid; idx < 16384; idx += THREADS) {
        int hi = idx >> 8, rem = idx & 255, m = rem >> 1, c = rem & 1;
        // W1kp[k2][j][c] = W1[j][2*k2+c]
        W1kp[idx] = W1g[m * 128 + (hi * 2 + c)];
        // W1jp[j2][k][c] = W1[2*j2+c][k]
        W1jp[idx] = W1g[(hi * 2 + c) * 128 + m];
    }
    for (int idx = tid; idx < 2560; idx += THREADS) {
        int i2 = idx >> 8, rem = idx & 255, j = rem >> 1, c = rem & 1;
        int i = i2 * 2 + c;
        W0kp[idx] = (i < 19) ? W0g[j * 19 + i] : 0.0f;
    }
    for (int idx = tid; idx < 128 * 19; idx += THREADS) {
        int j = idx / 19;
        int i = idx - j * 19;
        W0T[(i << 7) + j] = W0g[idx];
    }
    if (tid < 128) {
        b0s[tid] = b0g[tid];
        b1s[tid] = b1g[tid];
        Wos[tid] = Wog[tid];
    }
    __syncthreads();

    const int w    = tid >> 5;
    const int lane = tid & 31;
    float* buf = sm + OFF_STAGE + w * WARP_STAGE;  // a0 then d1 [p][128]
    float* hs  = buf + 1024;                        // [p][20]
    float* dEs = hs + 160;                          // [p][48]

    const int e    = lane & 15;
    const int half = lane >> 4;
    const int j0   = lane << 2;

    float b0a[4], b1a[4], woa[4];
    *(float4*)b0a = *(const float4*)(b0s + j0);
    *(float4*)b1a = *(const float4*)(b1s + j0);
    *(float4*)woa = *(const float4*)(Wos + j0);
    const float bo_r = __ldg(bog);

    const int gw = blockIdx.x * NWARP + w;
    const int nw = gridDim.x * NWARP;

    for (int n0 = gw * PB; n0 < n_pts; n0 += nw * PB) {

        // ================= gather: 8 points =================
        #pragma unroll
        for (int p = 0; p < PB; p++) {
            int n = n0 + p;
            int nc = (n < n_pts) ? n : (n_pts - 1);
            float px = fmaf(__ldg(pos + 3 * nc + 0), 0.5f, 0.5f);
            float py = fmaf(__ldg(pos + 3 * nc + 1), 0.5f, 0.5f);
            float pz = fmaf(__ldg(pos + 3 * nc + 2), 0.5f, 0.5f);
            float xx = px * 127.0f, xy = py * 127.0f, xz = pz * 127.0f;
            int ix = min(126, max(0, (int)floorf(xx)));
            int iy = min(126, max(0, (int)floorf(xy)));
            int iz = min(126, max(0, (int)floorf(xz)));
            float fx = xx - (float)ix;
            float fy = xy - (float)iy;
            float fz = xz - (float)iz;
            int base = ((ix << 7) + iy) * 128 + iz;

            float emb = 0.f, dex = 0.f, dey = 0.f, dez = 0.f;
            #pragma unroll
            for (int cc = 0; cc < 4; cc++) {
                int c  = (half << 2) + cc;
                int dx = (c >> 2) & 1, dy = (c >> 1) & 1, dz = c & 1;
                float wx = dx ? fx : 1.0f - fx;
                float wy = dy ? fy : 1.0f - fy;
                float wz = dz ? fz : 1.0f - fz;
                int gi = base + (dx << 14) + (dy << 7) + dz;
                float g = __ldg(grid + (gi << 4) + e);
                float wyz = wy * wz, wxz = wx * wz, wxy = wx * wy;
                emb = fmaf(g, wx * wyz, emb);
                float gyz = g * wyz, gxz = g * wxz, gxy = g * wxy;
                dex += dx ? gyz : -gyz;
                dey += dy ? gxz : -gxz;
                dez += dz ? gxy : -gxy;
            }
            emb += shx(emb, 16);
            dex += shx(dex, 16);
            dey += shx(dey, 16);
            dez += shx(dez, 16);

            if (lane < 16) {
                hs[p * 20 + e]       = emb;
                dEs[p * 48 + e]      = dex * 127.0f;
                dEs[p * 48 + 16 + e] = dey * 127.0f;
                dEs[p * 48 + 32 + e] = dez * 127.0f;
            } else if (lane == 16) {
                *(float4*)(hs + p * 20 + 16) = make_float4(px, py, pz, 0.0f);
            }
        }
        __syncwarp();

        // ================= layer 0 forward (packed over k) =================
        u64 z0p[PB][4];
        #pragma unroll
        for (int p = 0; p < PB; p++) {
            z0p[p][0] = 0ull; z0p[p][1] = 0ull; z0p[p][2] = 0ull; z0p[p][3] = 0ull;
        }
        #pragma unroll
        for (int kc = 0; kc < 5; kc++) {          // 4 inputs per chunk
            const float* wb = W0kp + kc * 512 + (j0 << 1);
            ulonglong2 wA  = *(const ulonglong2*)(wb);        // k even pair: j0,j1
            ulonglong2 wA2 = *(const ulonglong2*)(wb + 4);    // j2,j3
            ulonglong2 wB  = *(const ulonglong2*)(wb + 256);  // k odd pair
            ulonglong2 wB2 = *(const ulonglong2*)(wb + 260);
            #pragma unroll
            for (int p = 0; p < PB; p++) {
                ulonglong2 av = *(const ulonglong2*)(hs + p * 20 + kc * 4);
                ffma2(z0p[p][0], wA.x,  av.x);
                ffma2(z0p[p][1], wA.y,  av.x);
                ffma2(z0p[p][2], wA2.x, av.x);
                ffma2(z0p[p][3], wA2.y, av.x);
                ffma2(z0p[p][0], wB.x,  av.y);
                ffma2(z0p[p][1], wB.y,  av.y);
                ffma2(z0p[p][2], wB2.x, av.y);
                ffma2(z0p[p][3], wB2.y, av.y);
            }
        }
        float c0r[PB][4];
        #pragma unroll
        for (int p = 0; p < PB; p++) {
            float4 s;
            float z0, z1_, z2, z3;
            z0 = hadd2(z0p[p][0]) + b0a[0];
            z1_= hadd2(z0p[p][1]) + b0a[1];
            z2 = hadd2(z0p[p][2]) + b0a[2];
            z3 = hadd2(z0p[p][3]) + b0a[3];
            __sincosf(30.0f * z0,  &s.x, &c0r[p][0]);
            __sincosf(30.0f * z1_, &s.y, &c0r[p][1]);
            __sincosf(30.0f * z2,  &s.z, &c0r[p][2]);
            __sincosf(30.0f * z3,  &s.w, &c0r[p][3]);
            *(float4*)(buf + p * 128 + j0) = s;
        }
        __syncwarp();

        // ================= layer 1 forward (packed over k) =================
        u64 z1p[PB][4];
        #pragma unroll
        for (int p = 0; p < PB; p++) {
            z1p[p][0] = 0ull; z1p[p][1] = 0ull; z1p[p][2] = 0ull; z1p[p][3] = 0ull;
        }
        #pragma unroll 2
        for (int kc = 0; kc < 32; kc++) {         // 4 k per chunk
            const float* wb = W1kp + kc * 512 + (j0 << 1);
            ulonglong2 wA  = *(const ulonglong2*)(wb);
            ulonglong2 wA2 = *(const ulonglong2*)(wb + 4);
            ulonglong2 wB  = *(const ulonglong2*)(wb + 256);
            ulonglong2 wB2 = *(const ulonglong2*)(wb + 260);
            #pragma unroll
            for (int p = 0; p < PB; p++) {
                ulonglong2 av = *(const ulonglong2*)(buf + p * 128 + kc * 4);
                ffma2(z1p[p][0], wA.x,  av.x);
                ffma2(z1p[p][1], wA.y,  av.x);
                ffma2(z1p[p][2], wA2.x, av.x);
                ffma2(z1p[p][3], wA2.y, av.x);
                ffma2(z1p[p][0], wB.x,  av.y);
                ffma2(z1p[p][1], wB.y,  av.y);
                ffma2(z1p[p][2], wB2.x, av.y);
                ffma2(z1p[p][3], wB2.y, av.y);
            }
        }
        __syncwarp();   // all a0 reads done before d1 overwrites buf

        // ================= head + d1 =================
        float sdf[PB];
        #pragma unroll
        for (int p = 0; p < PB; p++) {
            float s1[4], c1[4];
            float z0_ = hadd2(z1p[p][0]) + b1a[0];
            float z1_ = hadd2(z1p[p][1]) + b1a[1];
            float z2_ = hadd2(z1p[p][2]) + b1a[2];
            float z3_ = hadd2(z1p[p][3]) + b1a[3];
            __sincosf(30.0f * z0_, &s1[0], &c1[0]);
            __sincosf(30.0f * z1_, &s1[1], &c1[1]);
            __sincosf(30.0f * z2_, &s1[2], &c1[2]);
            __sincosf(30.0f * z3_, &s1[3], &c1[3]);
            float sp = woa[0]*s1[0] + woa[1]*s1[1] + woa[2]*s1[2] + woa[3]*s1[3];
            #pragma unroll
            for (int m = 16; m; m >>= 1) sp += shx(sp, m);
            sdf[p] = sp + bo_r;
            *(float4*)(buf + p * 128 + j0) =
                make_float4(woa[0]*30.0f*c1[0], woa[1]*30.0f*c1[1],
                            woa[2]*30.0f*c1[2], woa[3]*30.0f*c1[3]);
        }
        __syncwarp();

        // ================= backward through W1 (packed over j) =================
        u64 g0p[PB][4];
        #pragma unroll
        for (int p = 0; p < PB; p++) {
            g0p[p][0] = 0ull; g0p[p][1] = 0ull; g0p[p][2] = 0ull; g0p[p][3] = 0ull;
        }
        #pragma unroll 2
        for (int jc = 0; jc < 32; jc++) {         // 4 j per chunk
            const float* wb = W1jp + jc * 512 + (j0 << 1);
            ulonglong2 wA  = *(const ulonglong2*)(wb);
            ulonglong2 wA2 = *(const ulonglong2*)(wb + 4);
            ulonglong2 wB  = *(const ulonglong2*)(wb + 256);
            ulonglong2 wB2 = *(const ulonglong2*)(wb + 260);
            #pragma unroll
            for (int p = 0; p < PB; p++) {
                ulonglong2 dv = *(const ulonglong2*)(buf + p * 128 + jc * 4);
                ffma2(g0p[p][0], wA.x,  dv.x);
                ffma2(g0p[p][1], wA.y,  dv.x);
                ffma2(g0p[p][2], wA2.x, dv.x);
                ffma2(g0p[p][3], wA2.y, dv.x);
                ffma2(g0p[p][0], wB.x,  dv.y);
                ffma2(g0p[p][1], wB.y,  dv.y);
                ffma2(g0p[p][2], wB2.x, dv.y);
                ffma2(g0p[p][3], wB2.y, dv.y);
            }
        }
        // d0 = g0 * 30 * cos(30 z0)
        float d0[PB][4];
        #pragma unroll
        for (int p = 0; p < PB; p++) {
            d0[p][0] = hadd2(g0p[p][0]) * (30.0f * c0r[p][0]);
            d0[p][1] = hadd2(g0p[p][1]) * (30.0f * c0r[p][1]);
            d0[p][2] = hadd2(g0p[p][2]) * (30.0f * c0r[p][2]);
            d0[p][3] = hadd2(g0p[p][3]) * (30.0f * c0r[p][3]);
        }

        // ===== backward through W0 fused with gradient dot =====
        float gx[PB], gy[PB], gz[PB];
        #pragma unroll
        for (int p = 0; p < PB; p++) { gx[p] = 0.f; gy[p] = 0.f; gz[p] = 0.f; }

        #pragma unroll
        for (int i = 0; i < 16; i++) {
            float4 w4 = *(const float4*)(W0T + i * 128 + j0);
            #pragma unroll
            for (int p = 0; p < PB; p++) {
                float t = w4.x*d0[p][0] + w4.y*d0[p][1] + w4.z*d0[p][2] + w4.w*d0[p][3];
                gx[p] = fmaf(t, dEs[p * 48 + i],      gx[p]);
                gy[p] = fmaf(t, dEs[p * 48 + 16 + i], gy[p]);
                gz[p] = fmaf(t, dEs[p * 48 + 32 + i], gz[p]);
            }
        }
        {
            float4 wx4 = *(const float4*)(W0T + 16 * 128 + j0);
            float4 wy4 = *(const float4*)(W0T + 17 * 128 + j0);
            float4 wz4 = *(const float4*)(W0T + 18 * 128 + j0);
            #pragma unroll
            for (int p = 0; p < PB; p++) {
                gx[p] += wx4.x*d0[p][0] + wx4.y*d0[p][1] + wx4.z*d0[p][2] + wx4.w*d0[p][3];
                gy[p] += wy4.x*d0[p][0] + wy4.y*d0[p][1] + wy4.z*d0[p][2] + wy4.w*d0[p][3];
                gz[p] += wz4.x*d0[p][0] + wz4.y*d0[p][1] + wz4.z*d0[p][2] + wz4.w*d0[p][3];
            }
        }
        #pragma unroll
        for (int p = 0; p < PB; p++) {
            #pragma unroll
            for (int m = 16; m; m >>= 1) {
                gx[p] += shx(gx[p], m);
                gy[p] += shx(gy[p], m);
                gz[p] += shx(gz[p], m);
            }
        }

        if (lane == 0) {
            #pragma unroll
            for (int p = 0; p < PB; p++) {
                int n = n0 + p;
                if (n < n_pts) {
                    out[n] = sdf[p];
                    float* go = out + n_pts + 3 * n;
                    go[0] = gx[p]; go[1] = gy[p]; go[2] = gz[p];
                }
            }
        }
        __syncwarp();
    }
}

extern "C" void kernel_launch(void* const* d_in, const int* in_sizes, int n_in,
                              void* d_out, int out_size) {
    const float* pos  = (const float*)d_in[0];
    const float* grid = (const float*)d_in[1];
    const float* W0   = (const float*)d_in[2];
    const float* b0   = (const float*)d_in[3];
    const float* W1   = (const float*)d_in[4];
    const float* b1   = (const float*)d_in[5];
    const float* Wo   = (const float*)d_in[6];
    const float* bo   = (const float*)d_in[7];
    int n_pts = in_sizes[0] / 3;

    size_t smem = (size_t)SMEM_FLOATS * sizeof(float);
    cudaFuncSetAttribute(neural_sdf_kernel,
                         cudaFuncAttributeMaxDynamicSharedMemorySize, (int)smem);
    neural_sdf_kernel<<<148, THREADS, smem>>>(pos, grid, W0, b0, W1, b1, Wo, bo,
                                              (float*)d_out, n_pts);
}